// round 4
// baseline (speedup 1.0000x reference)
#include <cuda_runtime.h>
#include <math.h>

#define NN 100000
#define EE 1600000
#define NB 98   // ceil(NN/1024)

// ---------------- scratch (static device globals; no runtime alloc) ----------------
__device__ int   g_cnt[NN];
__device__ int   g_rowptr[NN + 1];
__device__ int   g_wp[NN];
__device__ int   g_cols[EE];
__device__ int   g_bsum[NB];
__device__ float g_dinv[NN];
__device__ float g_h1[NN * 128];   // x @ W1
__device__ float g_a1[NN * 128];   // relu(Ahat h1 + b1)
__device__ float g_h2[NN * 64];    // a1 @ W2

// ---------------- CSR build ----------------
__global__ void k_clear() {
    int i = blockIdx.x * blockDim.x + threadIdx.x;
    if (i < NN) g_cnt[i] = 0;
}

__global__ void k_count(const int* __restrict__ dst) {
    int e = blockIdx.x * blockDim.x + threadIdx.x;
    if (e < EE) atomicAdd(&g_cnt[dst[e]], 1);
}

__global__ void k_scan_block() {
    __shared__ int s[1024];
    int idx = blockIdx.x * 1024 + threadIdx.x;
    int v = (idx < NN) ? g_cnt[idx] : 0;
    s[threadIdx.x] = v;
    __syncthreads();
    #pragma unroll
    for (int off = 1; off < 1024; off <<= 1) {
        int t = (threadIdx.x >= off) ? s[threadIdx.x - off] : 0;
        __syncthreads();
        s[threadIdx.x] += t;
        __syncthreads();
    }
    if (idx < NN) g_rowptr[idx] = s[threadIdx.x] - v;   // block-local exclusive
    if (threadIdx.x == 1023) g_bsum[blockIdx.x] = s[1023];
}

__global__ void k_scan_sums() {
    int acc = 0;
    for (int i = 0; i < NB; i++) { int t = g_bsum[i]; g_bsum[i] = acc; acc += t; }
}

__global__ void k_finalize() {
    int i = blockIdx.x * blockDim.x + threadIdx.x;
    if (i < NN) {
        int rp = g_rowptr[i] + g_bsum[i >> 10];
        g_rowptr[i] = rp;
        g_wp[i] = rp;
        g_dinv[i] = rsqrtf((float)(g_cnt[i] + 1));   // +1 self loop
    }
    if (i == 0) g_rowptr[NN] = EE;
}

__global__ void k_scatter(const int* __restrict__ src, const int* __restrict__ dst) {
    int e = blockIdx.x * blockDim.x + threadIdx.x;
    if (e < EE) {
        int p = atomicAdd(&g_wp[dst[e]], 1);
        g_cols[p] = src[e];
    }
}

// ---------------- register-tiled SGEMM (K = 128 fixed) ----------------
// BM=128, BK=8, 256 threads; thread microtile TM=8 x TN (8 for BN=128, 4 for BN=64)
template <int BN, int TN>
__device__ __forceinline__ void sgemm_body(const float* __restrict__ A,
                                           const float* __restrict__ B,
                                           float* __restrict__ C) {
    constexpr int BM = 128, BK = 8, TM = 8;
    __shared__ float As[BK][BM + 4];
    __shared__ float Bs[BK][BN];

    const int tid = threadIdx.x;
    const int tx = tid & 15;          // 16 col groups
    const int ty = tid >> 4;          // 16 row groups
    const int blockRow = blockIdx.x * BM;

    float acc[TM][TN];
    #pragma unroll
    for (int i = 0; i < TM; i++)
        #pragma unroll
        for (int j = 0; j < TN; j++) acc[i][j] = 0.f;

    const int ar = tid >> 1;          // row within A tile (0..127)
    const int aseg = tid & 1;         // which float4 in the 8-wide k slab

    for (int kt = 0; kt < 128; kt += BK) {
        // load A tile (128 rows x 8 k), transposed into As[k][row]
        float4 av = make_float4(0.f, 0.f, 0.f, 0.f);
        int grow = blockRow + ar;
        if (grow < NN)
            av = *reinterpret_cast<const float4*>(A + grow * 128 + kt + aseg * 4);
        As[aseg * 4 + 0][ar] = av.x;
        As[aseg * 4 + 1][ar] = av.y;
        As[aseg * 4 + 2][ar] = av.z;
        As[aseg * 4 + 3][ar] = av.w;

        // load B tile (8 rows x BN)
        if (BN == 128) {
            int br = tid >> 5, bc = tid & 31;
            *reinterpret_cast<float4*>(&Bs[br][bc * 4]) =
                *reinterpret_cast<const float4*>(B + (kt + br) * BN + bc * 4);
        } else {
            if (tid < 128) {
                int br = tid >> 4, bc = tid & 15;
                *reinterpret_cast<float4*>(&Bs[br][bc * 4]) =
                    *reinterpret_cast<const float4*>(B + (kt + br) * BN + bc * 4);
            }
        }
        __syncthreads();

        #pragma unroll
        for (int k = 0; k < BK; k++) {
            float ra[TM], rb[TN];
            #pragma unroll
            for (int i = 0; i < TM; i++) ra[i] = As[k][ty * TM + i];
            #pragma unroll
            for (int j = 0; j < TN; j++) rb[j] = Bs[k][tx * TN + j];
            #pragma unroll
            for (int i = 0; i < TM; i++)
                #pragma unroll
                for (int j = 0; j < TN; j++) acc[i][j] += ra[i] * rb[j];
        }
        __syncthreads();
    }

    #pragma unroll
    for (int i = 0; i < TM; i++) {
        int row = blockRow + ty * TM + i;
        if (row < NN) {
            #pragma unroll
            for (int j = 0; j < TN; j += 4) {
                float4 v = make_float4(acc[i][j], acc[i][j + 1], acc[i][j + 2], acc[i][j + 3]);
                *reinterpret_cast<float4*>(C + row * BN + tx * TN + j) = v;
            }
        }
    }
}

__global__ void __launch_bounds__(256) k_gemm1(const float* __restrict__ x,
                                               const float* __restrict__ W1) {
    sgemm_body<128, 8>(x, W1, g_h1);
}

__global__ void __launch_bounds__(256) k_gemm2(const float* __restrict__ W2) {
    sgemm_body<64, 4>(g_a1, W2, g_h2);
}

// ---------------- aggregation layer 1: out = relu(dv*(sum h*dinv) + b1) ----------------
__global__ void k_agg1(const float* __restrict__ b1) {
    int gw = (blockIdx.x * blockDim.x + threadIdx.x) >> 5;
    int lane = threadIdx.x & 31;
    if (gw >= NN) return;

    float dv = g_dinv[gw];
    const float4* hp = reinterpret_cast<const float4*>(g_h1);

    float4 acc = hp[gw * 32 + lane];   // self loop: h[v]*dv (outer *dv applied at end)
    acc.x *= dv; acc.y *= dv; acc.z *= dv; acc.w *= dv;

    int e = g_rowptr[gw], s1 = g_rowptr[gw + 1];
    for (; e + 2 <= s1; e += 2) {
        int sa = g_cols[e], sb = g_cols[e + 1];
        float da = g_dinv[sa], db = g_dinv[sb];
        float4 ha = hp[sa * 32 + lane];
        float4 hb = hp[sb * 32 + lane];
        acc.x += ha.x * da + hb.x * db;
        acc.y += ha.y * da + hb.y * db;
        acc.z += ha.z * da + hb.z * db;
        acc.w += ha.w * da + hb.w * db;
    }
    if (e < s1) {
        int sa = g_cols[e];
        float da = g_dinv[sa];
        float4 ha = hp[sa * 32 + lane];
        acc.x += ha.x * da; acc.y += ha.y * da;
        acc.z += ha.z * da; acc.w += ha.w * da;
    }

    float4 bb = reinterpret_cast<const float4*>(b1)[lane];
    float4 r;
    r.x = fmaxf(acc.x * dv + bb.x, 0.f);
    r.y = fmaxf(acc.y * dv + bb.y, 0.f);
    r.z = fmaxf(acc.z * dv + bb.z, 0.f);
    r.w = fmaxf(acc.w * dv + bb.w, 0.f);
    reinterpret_cast<float4*>(g_a1)[gw * 32 + lane] = r;
}

// ---------------- aggregation layer 2 + bias + log_softmax ----------------
__global__ void k_agg2(const float* __restrict__ b2, float* __restrict__ out) {
    int gw = (blockIdx.x * blockDim.x + threadIdx.x) >> 5;
    int lane = threadIdx.x & 31;
    if (gw >= NN) return;

    float dv = g_dinv[gw];
    const float2* hp = reinterpret_cast<const float2*>(g_h2);

    float2 acc = hp[gw * 32 + lane];
    acc.x *= dv; acc.y *= dv;

    int e = g_rowptr[gw], s1 = g_rowptr[gw + 1];
    for (; e + 2 <= s1; e += 2) {
        int sa = g_cols[e], sb = g_cols[e + 1];
        float da = g_dinv[sa], db = g_dinv[sb];
        float2 ha = hp[sa * 32 + lane];
        float2 hb = hp[sb * 32 + lane];
        acc.x += ha.x * da + hb.x * db;
        acc.y += ha.y * da + hb.y * db;
    }
    if (e < s1) {
        int sa = g_cols[e];
        float da = g_dinv[sa];
        float2 ha = hp[sa * 32 + lane];
        acc.x += ha.x * da; acc.y += ha.y * da;
    }

    float2 bb = reinterpret_cast<const float2*>(b2)[lane];
    float vx = acc.x * dv + bb.x;
    float vy = acc.y * dv + bb.y;

    // log_softmax over the 64 values (2 per lane)
    float m = fmaxf(vx, vy);
    #pragma unroll
    for (int o = 16; o > 0; o >>= 1) m = fmaxf(m, __shfl_xor_sync(0xffffffffu, m, o));
    float s = expf(vx - m) + expf(vy - m);
    #pragma unroll
    for (int o = 16; o > 0; o >>= 1) s += __shfl_xor_sync(0xffffffffu, s, o);
    float lse = m + logf(s);

    float2 o2 = make_float2(vx - lse, vy - lse);
    reinterpret_cast<float2*>(out)[gw * 32 + lane] = o2;
}

// ---------------- launch ----------------
extern "C" void kernel_launch(void* const* d_in, const int* in_sizes, int n_in,
                              void* d_out, int out_size) {
    const float* x  = (const float*)d_in[0];
    const int*   ei = (const int*)d_in[1];
    const float* W1 = (const float*)d_in[2];
    const float* b1 = (const float*)d_in[3];
    const float* W2 = (const float*)d_in[4];
    const float* b2 = (const float*)d_in[5];
    float* out = (float*)d_out;

    const int* src = ei;        // edge_index[0, :]
    const int* dst = ei + EE;   // edge_index[1, :]

    // CSR build (per-launch, deterministic up to fp-order in rows)
    k_clear<<<(NN + 255) / 256, 256>>>();
    k_count<<<(EE + 255) / 256, 256>>>(dst);
    k_scan_block<<<NB, 1024>>>();
    k_scan_sums<<<1, 1>>>();
    k_finalize<<<(NN + 255) / 256, 256>>>();
    k_scatter<<<(EE + 255) / 256, 256>>>(src, dst);

    const int gemm_blocks = (NN + 127) / 128;      // 782
    const int agg_blocks  = (NN * 32 + 255) / 256; // 12500 (warp per node)

    k_gemm1<<<gemm_blocks, 256>>>(x, W1);
    k_agg1<<<agg_blocks, 256>>>(b1);
    k_gemm2<<<gemm_blocks, 256>>>(W2);
    k_agg2<<<agg_blocks, 256>>>(b2, out);
}

// round 5
// speedup vs baseline: 1.0879x; 1.0879x over previous
#include <cuda_runtime.h>
#include <math.h>

#define NN 100000
#define EE 1600000
#define NB 98   // ceil(NN/1024)

// ---------------- scratch (static device globals; no runtime alloc) ----------------
__device__ int   g_cnt[NN];
__device__ int   g_rowptr[NN + 1];
__device__ int   g_wp[NN];
__device__ int   g_cols[EE];
__device__ int   g_bsum[NB];
__device__ float g_dinv[NN];
__device__ float g_h1[NN * 128];   // x @ W1
__device__ float g_a1[NN * 128];   // relu(Ahat h1 + b1)
__device__ float g_h2[NN * 64];    // a1 @ W2

// ---------------- CSR build ----------------
__global__ void k_clear() {
    int i = blockIdx.x * blockDim.x + threadIdx.x;
    if (i < NN) g_cnt[i] = 0;
}

__global__ void k_count(const int* __restrict__ dst) {
    int e = blockIdx.x * blockDim.x + threadIdx.x;
    if (e < EE) atomicAdd(&g_cnt[dst[e]], 1);
}

__global__ void k_scan_block() {
    __shared__ int s[1024];
    int idx = blockIdx.x * 1024 + threadIdx.x;
    int v = (idx < NN) ? g_cnt[idx] : 0;
    s[threadIdx.x] = v;
    __syncthreads();
    #pragma unroll
    for (int off = 1; off < 1024; off <<= 1) {
        int t = (threadIdx.x >= off) ? s[threadIdx.x - off] : 0;
        __syncthreads();
        s[threadIdx.x] += t;
        __syncthreads();
    }
    if (idx < NN) g_rowptr[idx] = s[threadIdx.x] - v;   // block-local exclusive
    if (threadIdx.x == 1023) g_bsum[blockIdx.x] = s[1023];
}

// parallel exclusive scan of the 98 block sums (was a 1-thread serial loop, 8.5us)
__global__ void k_scan_sums() {
    __shared__ int s[128];
    int tid = threadIdx.x;
    int v = (tid < NB) ? g_bsum[tid] : 0;
    s[tid] = v;
    __syncthreads();
    #pragma unroll
    for (int off = 1; off < 128; off <<= 1) {
        int t = (tid >= off) ? s[tid - off] : 0;
        __syncthreads();
        s[tid] += t;
        __syncthreads();
    }
    if (tid < NB) g_bsum[tid] = s[tid] - v;   // exclusive
}

__global__ void k_finalize() {
    int i = blockIdx.x * blockDim.x + threadIdx.x;
    if (i < NN) {
        int rp = g_rowptr[i] + g_bsum[i >> 10];
        g_rowptr[i] = rp;
        g_wp[i] = rp;
        g_dinv[i] = rsqrtf((float)(g_cnt[i] + 1));   // +1 self loop
    }
    if (i == 0) g_rowptr[NN] = EE;
}

__global__ void k_scatter(const int* __restrict__ src, const int* __restrict__ dst) {
    int e = blockIdx.x * blockDim.x + threadIdx.x;
    if (e < EE) {
        int p = atomicAdd(&g_wp[dst[e]], 1);
        g_cols[p] = src[e];
    }
}

// ---------------- double-buffered register-tiled SGEMM (K = 128 fixed) ----------------
// BM=128, BK=8, 256 threads; thread microtile TM=8 x TN (8 for BN=128, 4 for BN=64)
template <int BN, int TN>
__device__ __forceinline__ void sgemm_body(const float* __restrict__ A,
                                           const float* __restrict__ B,
                                           float* __restrict__ C) {
    constexpr int BM = 128, BK = 8, TM = 8;
    __shared__ float As[2][BK][BM + 4];
    __shared__ float Bs[2][BK][BN];

    const int tid = threadIdx.x;
    const int tx = tid & 15;          // 16 col groups
    const int ty = tid >> 4;          // 16 row groups
    const int blockRow = blockIdx.x * BM;

    const int ar = tid >> 1;          // row within A tile (0..127)
    const int aseg = tid & 1;         // which float4 of the 8-wide k slab
    const int grow = blockRow + ar;
    const bool arow_ok = (grow < NN);
    const float* aptr = A + (size_t)(arow_ok ? grow : 0) * 128 + aseg * 4;

    // B-tile staging coordinates
    const int br = (BN == 128) ? (tid >> 5) : (tid >> 4);
    const int bc = (BN == 128) ? (tid & 31) : (tid & 15);
    const bool bld = (BN == 128) ? true : (tid < 128);

    float acc[TM][TN];
    #pragma unroll
    for (int i = 0; i < TM; i++)
        #pragma unroll
        for (int j = 0; j < TN; j++) acc[i][j] = 0.f;

    // ---- prologue: stage K-tile 0 into buffer 0 ----
    {
        float4 av = make_float4(0.f, 0.f, 0.f, 0.f);
        if (arow_ok) av = *reinterpret_cast<const float4*>(aptr);
        As[0][aseg * 4 + 0][ar] = av.x;
        As[0][aseg * 4 + 1][ar] = av.y;
        As[0][aseg * 4 + 2][ar] = av.z;
        As[0][aseg * 4 + 3][ar] = av.w;
        if (bld)
            *reinterpret_cast<float4*>(&Bs[0][br][bc * 4]) =
                *reinterpret_cast<const float4*>(B + br * BN + bc * 4);
    }
    __syncthreads();

    #pragma unroll 1
    for (int t = 0; t < 16; t++) {          // 128 / BK = 16 K-tiles
        const int cur = t & 1, nxt = cur ^ 1;
        const int ktn = (t + 1) * BK;
        const bool more = (t < 15);

        // stage next tile global->regs (overlaps with FFMA below)
        float4 av2 = make_float4(0.f, 0.f, 0.f, 0.f);
        float4 bv2 = make_float4(0.f, 0.f, 0.f, 0.f);
        if (more) {
            if (arow_ok) av2 = *reinterpret_cast<const float4*>(aptr + ktn);
            if (bld)
                bv2 = *reinterpret_cast<const float4*>(B + (ktn + br) * BN + bc * 4);
        }

        // compute on current buffer
        #pragma unroll
        for (int k = 0; k < BK; k++) {
            float ra[TM], rb[TN];
            #pragma unroll
            for (int i = 0; i < TM; i++) ra[i] = As[cur][k][ty * TM + i];
            #pragma unroll
            for (int j = 0; j < TN; j++) rb[j] = Bs[cur][k][tx * TN + j];
            #pragma unroll
            for (int i = 0; i < TM; i++)
                #pragma unroll
                for (int j = 0; j < TN; j++) acc[i][j] += ra[i] * rb[j];
        }

        // regs -> next buffer
        if (more) {
            As[nxt][aseg * 4 + 0][ar] = av2.x;
            As[nxt][aseg * 4 + 1][ar] = av2.y;
            As[nxt][aseg * 4 + 2][ar] = av2.z;
            As[nxt][aseg * 4 + 3][ar] = av2.w;
            if (bld)
                *reinterpret_cast<float4*>(&Bs[nxt][br][bc * 4]) = bv2;
        }
        __syncthreads();
    }

    #pragma unroll
    for (int i = 0; i < TM; i++) {
        int row = blockRow + ty * TM + i;
        if (row < NN) {
            #pragma unroll
            for (int j = 0; j < TN; j += 4) {
                float4 v = make_float4(acc[i][j], acc[i][j + 1], acc[i][j + 2], acc[i][j + 3]);
                *reinterpret_cast<float4*>(C + (size_t)row * BN + tx * TN + j) = v;
            }
        }
    }
}

__global__ void __launch_bounds__(256) k_gemm1(const float* __restrict__ x,
                                               const float* __restrict__ W1) {
    sgemm_body<128, 8>(x, W1, g_h1);
}

__global__ void __launch_bounds__(256) k_gemm2(const float* __restrict__ W2) {
    sgemm_body<64, 4>(g_a1, W2, g_h2);
}

// ---------------- aggregation layer 1: out = relu(dv*(sum h*dinv) + b1) ----------------
__global__ void k_agg1(const float* __restrict__ b1) {
    int gw = (blockIdx.x * blockDim.x + threadIdx.x) >> 5;
    int lane = threadIdx.x & 31;
    if (gw >= NN) return;

    float dv = g_dinv[gw];
    const float4* hp = reinterpret_cast<const float4*>(g_h1);

    float4 acc = hp[gw * 32 + lane];   // self loop: h[v]*dv (outer *dv applied at end)
    acc.x *= dv; acc.y *= dv; acc.z *= dv; acc.w *= dv;

    int e = g_rowptr[gw], s1 = g_rowptr[gw + 1];
    for (; e + 2 <= s1; e += 2) {
        int sa = g_cols[e], sb = g_cols[e + 1];
        float da = g_dinv[sa], db = g_dinv[sb];
        float4 ha = hp[sa * 32 + lane];
        float4 hb = hp[sb * 32 + lane];
        acc.x += ha.x * da + hb.x * db;
        acc.y += ha.y * da + hb.y * db;
        acc.z += ha.z * da + hb.z * db;
        acc.w += ha.w * da + hb.w * db;
    }
    if (e < s1) {
        int sa = g_cols[e];
        float da = g_dinv[sa];
        float4 ha = hp[sa * 32 + lane];
        acc.x += ha.x * da; acc.y += ha.y * da;
        acc.z += ha.z * da; acc.w += ha.w * da;
    }

    float4 bb = reinterpret_cast<const float4*>(b1)[lane];
    float4 r;
    r.x = fmaxf(acc.x * dv + bb.x, 0.f);
    r.y = fmaxf(acc.y * dv + bb.y, 0.f);
    r.z = fmaxf(acc.z * dv + bb.z, 0.f);
    r.w = fmaxf(acc.w * dv + bb.w, 0.f);
    reinterpret_cast<float4*>(g_a1)[gw * 32 + lane] = r;
}

// ---------------- aggregation layer 2 + bias + log_softmax ----------------
__global__ void k_agg2(const float* __restrict__ b2, float* __restrict__ out) {
    int gw = (blockIdx.x * blockDim.x + threadIdx.x) >> 5;
    int lane = threadIdx.x & 31;
    if (gw >= NN) return;

    float dv = g_dinv[gw];
    const float2* hp = reinterpret_cast<const float2*>(g_h2);

    float2 acc = hp[gw * 32 + lane];
    acc.x *= dv; acc.y *= dv;

    int e = g_rowptr[gw], s1 = g_rowptr[gw + 1];
    for (; e + 2 <= s1; e += 2) {
        int sa = g_cols[e], sb = g_cols[e + 1];
        float da = g_dinv[sa], db = g_dinv[sb];
        float2 ha = hp[sa * 32 + lane];
        float2 hb = hp[sb * 32 + lane];
        acc.x += ha.x * da + hb.x * db;
        acc.y += ha.y * da + hb.y * db;
    }
    if (e < s1) {
        int sa = g_cols[e];
        float da = g_dinv[sa];
        float2 ha = hp[sa * 32 + lane];
        acc.x += ha.x * da; acc.y += ha.y * da;
    }

    float2 bb = reinterpret_cast<const float2*>(b2)[lane];
    float vx = acc.x * dv + bb.x;
    float vy = acc.y * dv + bb.y;

    // log_softmax over the 64 values (2 per lane)
    float m = fmaxf(vx, vy);
    #pragma unroll
    for (int o = 16; o > 0; o >>= 1) m = fmaxf(m, __shfl_xor_sync(0xffffffffu, m, o));
    float s = expf(vx - m) + expf(vy - m);
    #pragma unroll
    for (int o = 16; o > 0; o >>= 1) s += __shfl_xor_sync(0xffffffffu, s, o);
    float lse = m + logf(s);

    float2 o2 = make_float2(vx - lse, vy - lse);
    reinterpret_cast<float2*>(out)[gw * 32 + lane] = o2;
}

// ---------------- launch ----------------
extern "C" void kernel_launch(void* const* d_in, const int* in_sizes, int n_in,
                              void* d_out, int out_size) {
    const float* x  = (const float*)d_in[0];
    const int*   ei = (const int*)d_in[1];
    const float* W1 = (const float*)d_in[2];
    const float* b1 = (const float*)d_in[3];
    const float* W2 = (const float*)d_in[4];
    const float* b2 = (const float*)d_in[5];
    float* out = (float*)d_out;

    const int* src = ei;        // edge_index[0, :]
    const int* dst = ei + EE;   // edge_index[1, :]

    // Host-side objects created once on the first (uncaptured, eager) call.
    // No device memory is allocated here; streams/events are host resources.
    static cudaStream_t s_csr = nullptr;
    static cudaEvent_t  ev_fork = nullptr, ev_join = nullptr;
    if (s_csr == nullptr) {
        cudaStreamCreateWithFlags(&s_csr, cudaStreamNonBlocking);
        cudaEventCreateWithFlags(&ev_fork, cudaEventDisableTiming);
        cudaEventCreateWithFlags(&ev_join, cudaEventDisableTiming);
    }

    const int gemm_blocks = (NN + 127) / 128;      // 782
    const int agg_blocks  = (NN * 32 + 255) / 256; // 12500 (warp per node)

    // ---- fork: CSR build branch (s_csr) runs concurrently with GEMM1 (stream 0) ----
    cudaEventRecord(ev_fork, 0);
    cudaStreamWaitEvent(s_csr, ev_fork, 0);

    k_clear<<<(NN + 255) / 256, 256, 0, s_csr>>>();
    k_count<<<(EE + 255) / 256, 256, 0, s_csr>>>(dst);
    k_scan_block<<<NB, 1024, 0, s_csr>>>();
    k_scan_sums<<<1, 128, 0, s_csr>>>();
    k_finalize<<<(NN + 255) / 256, 256, 0, s_csr>>>();
    k_scatter<<<(EE + 255) / 256, 256, 0, s_csr>>>(src, dst);
    cudaEventRecord(ev_join, s_csr);

    // GEMM1 on the main stream, overlapping the CSR branch
    k_gemm1<<<gemm_blocks, 256>>>(x, W1);

    // ---- join: aggregation needs both GEMM1 output and the CSR structures ----
    cudaStreamWaitEvent(0, ev_join, 0);

    k_agg1<<<agg_blocks, 256>>>(b1);
    k_gemm2<<<gemm_blocks, 256>>>(W2);
    k_agg2<<<agg_blocks, 256>>>(b2, out);
}

// round 9
// speedup vs baseline: 1.1757x; 1.0807x over previous
#include <cuda_runtime.h>
#include <cuda_fp16.h>
#include <math.h>
#include <stdint.h>

#define NN 100000
#define EE 1600000
#define NB 98   // ceil(NN/1024)

// ---------------- scratch (static device globals; no runtime alloc) ----------------
__device__ int    g_cnt[NN];        // zero on load; re-zeroed by k_finalize each launch
__device__ int    g_rowptr[NN + 1];
__device__ int    g_wp[NN];
__device__ int    g_cols[EE];
__device__ int    g_bsum[NB];
__device__ float  g_dinv[NN];
__device__ __half g_h1h[NN * 128];  // x @ W1, fp16 (gathered by agg1)
__device__ float  g_a1[NN * 128];   // relu(Ahat h1 + b1), fp32 (dense GEMM2 input)
__device__ __half g_h2h[NN * 64];   // a1 @ W2, fp16 (gathered by agg2)

// ---------------- CSR build ----------------
__global__ void k_count(const int* __restrict__ dst) {
    int e = blockIdx.x * blockDim.x + threadIdx.x;   // indexes int2 pairs
    if (e < EE / 2) {
        int2 d = reinterpret_cast<const int2*>(dst)[e];
        atomicAdd(&g_cnt[d.x], 1);
        atomicAdd(&g_cnt[d.y], 1);
    }
}

__global__ void k_scan_block() {
    __shared__ int s[1024];
    int idx = blockIdx.x * 1024 + threadIdx.x;
    int v = (idx < NN) ? g_cnt[idx] : 0;
    s[threadIdx.x] = v;
    __syncthreads();
    #pragma unroll
    for (int off = 1; off < 1024; off <<= 1) {
        int t = (threadIdx.x >= off) ? s[threadIdx.x - off] : 0;
        __syncthreads();
        s[threadIdx.x] += t;
        __syncthreads();
    }
    if (idx < NN) g_rowptr[idx] = s[threadIdx.x] - v;   // block-local exclusive
    if (threadIdx.x == 1023) g_bsum[blockIdx.x] = s[1023];
}

__global__ void k_scan_sums() {
    __shared__ int s[128];
    int tid = threadIdx.x;
    int v = (tid < NB) ? g_bsum[tid] : 0;
    s[tid] = v;
    __syncthreads();
    #pragma unroll
    for (int off = 1; off < 128; off <<= 1) {
        int t = (tid >= off) ? s[tid - off] : 0;
        __syncthreads();
        s[tid] += t;
        __syncthreads();
    }
    if (tid < NB) g_bsum[tid] = s[tid] - v;   // exclusive
}

__global__ void k_finalize() {
    int i = blockIdx.x * blockDim.x + threadIdx.x;
    if (i < NN) {
        int c = g_cnt[i];
        int rp = g_rowptr[i] + g_bsum[i >> 10];
        g_rowptr[i] = rp;
        g_wp[i] = rp;
        g_dinv[i] = rsqrtf((float)(c + 1));   // +1 self loop
        g_cnt[i] = 0;                          // restore invariant for next replay
    }
    if (i == 0) g_rowptr[NN] = EE;
}

__global__ void k_scatter(const int* __restrict__ src, const int* __restrict__ dst) {
    int e = blockIdx.x * blockDim.x + threadIdx.x;
    if (e < EE) {
        int p = atomicAdd(&g_wp[dst[e]], 1);
        g_cols[p] = src[e];
    }
}

// ---------------- double-buffered register-tiled SGEMM, fp16 output (K = 128) ------
// BM=128, BK=8, 256 threads; thread microtile TM=8 x TN (8 for BN=128, 4 for BN=64)
template <int BN, int TN>
__device__ __forceinline__ void sgemm_body_h(const float* __restrict__ A,
                                             const float* __restrict__ B,
                                             __half* __restrict__ C) {
    constexpr int BM = 128, BK = 8, TM = 8;
    __shared__ float As[2][BK][BM + 4];
    __shared__ float Bs[2][BK][BN];

    const int tid = threadIdx.x;
    const int tx = tid & 15;          // 16 col groups
    const int ty = tid >> 4;          // 16 row groups
    const int blockRow = blockIdx.x * BM;

    const int ar = tid >> 1;
    const int aseg = tid & 1;
    const int grow = blockRow + ar;
    const bool arow_ok = (grow < NN);
    const float* aptr = A + (size_t)(arow_ok ? grow : 0) * 128 + aseg * 4;

    const int br = (BN == 128) ? (tid >> 5) : (tid >> 4);
    const int bc = (BN == 128) ? (tid & 31) : (tid & 15);
    const bool bld = (BN == 128) ? true : (tid < 128);

    float acc[TM][TN];
    #pragma unroll
    for (int i = 0; i < TM; i++)
        #pragma unroll
        for (int j = 0; j < TN; j++) acc[i][j] = 0.f;

    {   // prologue: stage K-tile 0 into buffer 0
        float4 av = make_float4(0.f, 0.f, 0.f, 0.f);
        if (arow_ok) av = *reinterpret_cast<const float4*>(aptr);
        As[0][aseg * 4 + 0][ar] = av.x;
        As[0][aseg * 4 + 1][ar] = av.y;
        As[0][aseg * 4 + 2][ar] = av.z;
        As[0][aseg * 4 + 3][ar] = av.w;
        if (bld)
            *reinterpret_cast<float4*>(&Bs[0][br][bc * 4]) =
                *reinterpret_cast<const float4*>(B + br * BN + bc * 4);
    }
    __syncthreads();

    #pragma unroll 1
    for (int t = 0; t < 16; t++) {
        const int cur = t & 1, nxt = cur ^ 1;
        const int ktn = (t + 1) * BK;
        const bool more = (t < 15);

        float4 av2 = make_float4(0.f, 0.f, 0.f, 0.f);
        float4 bv2 = make_float4(0.f, 0.f, 0.f, 0.f);
        if (more) {
            if (arow_ok) av2 = *reinterpret_cast<const float4*>(aptr + ktn);
            if (bld)
                bv2 = *reinterpret_cast<const float4*>(B + (ktn + br) * BN + bc * 4);
        }

        #pragma unroll
        for (int k = 0; k < BK; k++) {
            float ra[TM], rb[TN];
            #pragma unroll
            for (int i = 0; i < TM; i++) ra[i] = As[cur][k][ty * TM + i];
            #pragma unroll
            for (int j = 0; j < TN; j++) rb[j] = Bs[cur][k][tx * TN + j];
            #pragma unroll
            for (int i = 0; i < TM; i++)
                #pragma unroll
                for (int j = 0; j < TN; j++) acc[i][j] += ra[i] * rb[j];
        }

        if (more) {
            As[nxt][aseg * 4 + 0][ar] = av2.x;
            As[nxt][aseg * 4 + 1][ar] = av2.y;
            As[nxt][aseg * 4 + 2][ar] = av2.z;
            As[nxt][aseg * 4 + 3][ar] = av2.w;
            if (bld)
                *reinterpret_cast<float4*>(&Bs[nxt][br][bc * 4]) = bv2;
        }
        __syncthreads();
    }

    // epilogue: convert to fp16, vectorized store (TN halves = TN*2 bytes, aligned)
    #pragma unroll
    for (int i = 0; i < TM; i++) {
        int row = blockRow + ty * TM + i;
        if (row < NN) {
            __half2 hv[TN / 2];
            #pragma unroll
            for (int j = 0; j < TN; j += 2)
                hv[j / 2] = __floats2half2_rn(acc[i][j], acc[i][j + 1]);
            if (TN == 8)
                *reinterpret_cast<uint4*>(C + (size_t)row * BN + tx * TN) =
                    *reinterpret_cast<uint4*>(hv);
            else
                *reinterpret_cast<uint2*>(C + (size_t)row * BN + tx * TN) =
                    *reinterpret_cast<uint2*>(hv);
        }
    }
}

__global__ void __launch_bounds__(256) k_gemm1(const float* __restrict__ x,
                                               const float* __restrict__ W1) {
    sgemm_body_h<128, 8>(x, W1, g_h1h);
}

__global__ void __launch_bounds__(256) k_gemm2(const float* __restrict__ W2) {
    sgemm_body_h<64, 4>(g_a1, W2, g_h2h);
}

// ---------------- aggregation layer 1: a1 = relu(dv*(sum h1*dinv) + b1) ------------
// warp per node; lane handles 4 cols (8 bytes fp16 per gather)
__global__ void k_agg1(const float* __restrict__ b1) {
    int gw = (blockIdx.x * blockDim.x + threadIdx.x) >> 5;
    int lane = threadIdx.x & 31;
    if (gw >= NN) return;

    float dv = g_dinv[gw];
    const uint2* hp = reinterpret_cast<const uint2*>(g_h1h);   // 32 x uint2 per row

    uint2 su = hp[gw * 32 + lane];
    float2 s0 = __half22float2(*reinterpret_cast<__half2*>(&su.x));
    float2 s1 = __half22float2(*reinterpret_cast<__half2*>(&su.y));
    float4 acc = make_float4(s0.x * dv, s0.y * dv, s1.x * dv, s1.y * dv);

    int e = g_rowptr[gw], s1e = g_rowptr[gw + 1];
    for (; e + 2 <= s1e; e += 2) {
        int sa = g_cols[e], sb = g_cols[e + 1];
        float da = g_dinv[sa], db = g_dinv[sb];
        uint2 ua = hp[sa * 32 + lane];
        uint2 ub = hp[sb * 32 + lane];
        float2 a0 = __half22float2(*reinterpret_cast<__half2*>(&ua.x));
        float2 a1 = __half22float2(*reinterpret_cast<__half2*>(&ua.y));
        float2 c0 = __half22float2(*reinterpret_cast<__half2*>(&ub.x));
        float2 c1 = __half22float2(*reinterpret_cast<__half2*>(&ub.y));
        acc.x += a0.x * da + c0.x * db;
        acc.y += a0.y * da + c0.y * db;
        acc.z += a1.x * da + c1.x * db;
        acc.w += a1.y * da + c1.y * db;
    }
    if (e < s1e) {
        int sa = g_cols[e];
        float da = g_dinv[sa];
        uint2 ua = hp[sa * 32 + lane];
        float2 a0 = __half22float2(*reinterpret_cast<__half2*>(&ua.x));
        float2 a1 = __half22float2(*reinterpret_cast<__half2*>(&ua.y));
        acc.x += a0.x * da; acc.y += a0.y * da;
        acc.z += a1.x * da; acc.w += a1.y * da;
    }

    float4 bb = reinterpret_cast<const float4*>(b1)[lane];
    float4 r;
    r.x = fmaxf(acc.x * dv + bb.x, 0.f);
    r.y = fmaxf(acc.y * dv + bb.y, 0.f);
    r.z = fmaxf(acc.z * dv + bb.z, 0.f);
    r.w = fmaxf(acc.w * dv + bb.w, 0.f);
    reinterpret_cast<float4*>(g_a1)[gw * 32 + lane] = r;
}

// ---------------- aggregation layer 2 + bias + log_softmax -------------------------
// warp per node; lane handles 2 cols (4 bytes fp16 per gather)
__global__ void k_agg2(const float* __restrict__ b2, float* __restrict__ out) {
    int gw = (blockIdx.x * blockDim.x + threadIdx.x) >> 5;
    int lane = threadIdx.x & 31;
    if (gw >= NN) return;

    float dv = g_dinv[gw];
    const uint32_t* hp = reinterpret_cast<const uint32_t*>(g_h2h);   // 32 x uint per row

    uint32_t su = hp[gw * 32 + lane];
    float2 sf = __half22float2(*reinterpret_cast<__half2*>(&su));
    float2 acc = make_float2(sf.x * dv, sf.y * dv);

    int e = g_rowptr[gw], s1 = g_rowptr[gw + 1];
    for (; e + 2 <= s1; e += 2) {
        int sa = g_cols[e], sb = g_cols[e + 1];
        float da = g_dinv[sa], db = g_dinv[sb];
        uint32_t ua = hp[sa * 32 + lane];
        uint32_t ub = hp[sb * 32 + lane];
        float2 fa = __half22float2(*reinterpret_cast<__half2*>(&ua));
        float2 fb = __half22float2(*reinterpret_cast<__half2*>(&ub));
        acc.x += fa.x * da + fb.x * db;
        acc.y += fa.y * da + fb.y * db;
    }
    if (e < s1) {
        int sa = g_cols[e];
        float da = g_dinv[sa];
        uint32_t ua = hp[sa * 32 + lane];
        float2 fa = __half22float2(*reinterpret_cast<__half2*>(&ua));
        acc.x += fa.x * da; acc.y += fa.y * da;
    }

    float2 bb = reinterpret_cast<const float2*>(b2)[lane];
    float vx = acc.x * dv + bb.x;
    float vy = acc.y * dv + bb.y;

    float m = fmaxf(vx, vy);
    #pragma unroll
    for (int o = 16; o > 0; o >>= 1) m = fmaxf(m, __shfl_xor_sync(0xffffffffu, m, o));
    float s = expf(vx - m) + expf(vy - m);
    #pragma unroll
    for (int o = 16; o > 0; o >>= 1) s += __shfl_xor_sync(0xffffffffu, s, o);
    float lse = m + logf(s);

    float2 o2 = make_float2(vx - lse, vy - lse);
    reinterpret_cast<float2*>(out)[gw * 32 + lane] = o2;
}

// ---------------- launch ----------------
extern "C" void kernel_launch(void* const* d_in, const int* in_sizes, int n_in,
                              void* d_out, int out_size) {
    const float* x  = (const float*)d_in[0];
    const int*   ei = (const int*)d_in[1];
    const float* W1 = (const float*)d_in[2];
    const float* b1 = (const float*)d_in[3];
    const float* W2 = (const float*)d_in[4];
    const float* b2 = (const float*)d_in[5];
    float* out = (float*)d_out;

    const int* src = ei;        // edge_index[0, :]
    const int* dst = ei + EE;   // edge_index[1, :]

    static cudaStream_t s_csr = nullptr;
    static cudaEvent_t  ev_fork = nullptr, ev_join = nullptr;
    if (s_csr == nullptr) {
        cudaStreamCreateWithFlags(&s_csr, cudaStreamNonBlocking);
        cudaEventCreateWithFlags(&ev_fork, cudaEventDisableTiming);
        cudaEventCreateWithFlags(&ev_join, cudaEventDisableTiming);
    }

    const int gemm_blocks = (NN + 127) / 128;      // 782
    const int agg_blocks  = (NN * 32 + 255) / 256; // 12500 (warp per node)

    // ---- fork: CSR build branch (s_csr) runs concurrently with GEMM1 (stream 0) ----
    cudaEventRecord(ev_fork, 0);
    cudaStreamWaitEvent(s_csr, ev_fork, 0);

    k_count<<<(EE / 2 + 255) / 256, 256, 0, s_csr>>>(dst);
    k_scan_block<<<NB, 1024, 0, s_csr>>>();
    k_scan_sums<<<1, 128, 0, s_csr>>>();
    k_finalize<<<(NN + 255) / 256, 256, 0, s_csr>>>();
    k_scatter<<<(EE + 255) / 256, 256, 0, s_csr>>>(src, dst);
    cudaEventRecord(ev_join, s_csr);

    // GEMM1 on the main stream, overlapping the CSR branch
    k_gemm1<<<gemm_blocks, 256>>>(x, W1);

    // ---- join ----
    cudaStreamWaitEvent(0, ev_join, 0);

    k_agg1<<<agg_blocks, 256>>>(b1);
    k_gemm2<<<gemm_blocks, 256>>>(W2);
    k_agg2<<<agg_blocks, 256>>>(b2, out);
}